// round 14
// baseline (speedup 1.0000x reference)
#include <cuda_runtime.h>
#include <cstdint>

#define B_DIM 64
#define S_DIM 512
#define W_DIM 256
#define D_DIM 768
#define N_DIM 96
#define MT 128
#define KT 64
#define NUM_KT 12
#define THREADS 256

#define A_RS 144                      // A fp16 stage row stride
#define B_RS 1552                     // B resident row stride (768*2 + 16)
#define A_STAGE 18432                 // 128 * 144
#define SM_A 1024                     // after idx (512) + clsb (384)
#define SM_BB (SM_A + 2 * A_STAGE)    // 37888
#define SMEM_TOTAL (SM_BB + N_DIM * B_RS)   // 186880
#define EP_RS 100                     // epilogue smem row stride (floats)

// Pre-converted fp16 copy of clsw: [96][768] fp16 (linear, 1536 B rows)
__device__ __align__(16) unsigned char g_Bh[N_DIM * D_DIM * 2];

static __device__ __forceinline__ uint32_t smem_u32(const void* p) {
    uint32_t a;
    asm("{ .reg .u64 t; cvta.to.shared.u64 t, %1; cvt.u32.u64 %0, t; }" : "=r"(a) : "l"(p));
    return a;
}

static __device__ __forceinline__ void ldsm4(uint32_t* r, uint32_t addr) {
    asm volatile("ldmatrix.sync.aligned.m8n8.x4.shared.b16 {%0,%1,%2,%3}, [%4];"
                 : "=r"(r[0]), "=r"(r[1]), "=r"(r[2]), "=r"(r[3]) : "r"(addr));
}

static __device__ __forceinline__ void mma_f16(float* c, const uint32_t* a, const uint32_t* b) {
    asm volatile(
        "mma.sync.aligned.m16n8k16.row.col.f32.f16.f16.f32 "
        "{%0,%1,%2,%3}, {%4,%5,%6,%7}, {%8,%9}, {%0,%1,%2,%3};"
        : "+f"(c[0]), "+f"(c[1]), "+f"(c[2]), "+f"(c[3])
        : "r"(a[0]), "r"(a[1]), "r"(a[2]), "r"(a[3]), "r"(b[0]), "r"(b[1]));
}

static __device__ __forceinline__ uint2 cvt_f16x4(float4 v) {
    uint2 r;   // low half of each word = lower-k element
    asm("cvt.rn.f16x2.f32 %0, %1, %2;" : "=r"(r.x) : "f"(v.y), "f"(v.x));
    asm("cvt.rn.f16x2.f32 %0, %1, %2;" : "=r"(r.y) : "f"(v.w), "f"(v.z));
    return r;
}

static __device__ __forceinline__ void cp16(uint32_t dst, const void* src) {
    asm volatile("cp.async.cg.shared.global [%0], [%1], 16;" :: "r"(dst), "l"(src) : "memory");
}

// ---------- kernel 1: convert clsw fp32 -> fp16 scratch ----------
__global__ void cvtB_kernel(const float* __restrict__ clsw) {
    int i = blockIdx.x * blockDim.x + threadIdx.x;   // 18432 float4 chunks
    float4 v = ((const float4*)clsw)[i];
    ((uint2*)g_Bh)[i] = cvt_f16x4(v);
}

// ---------- kernel 2: gathered GEMM, B resident, coalesced epilogue ----------
__global__ __launch_bounds__(THREADS, 1)
void ner_hmma_kernel(const float* __restrict__ seq, const int* __restrict__ widx,
                     const float* __restrict__ clsb, float* __restrict__ out) {
    extern __shared__ char smem[];
    const uint32_t sb = smem_u32(smem);
    const int tid  = threadIdx.x;
    const int wid  = tid >> 5;
    const int lane = tid & 31;
    const int b  = blockIdx.x >> 1;
    const int w0 = (blockIdx.x & 1) * MT;

    int*   idx_s  = (int*)smem;                 // [0, 512)
    float* clsb_s = (float*)(smem + 512);       // [512, 896)
    if (tid < MT)    idx_s[tid]  = widx[b * W_DIM + w0 + tid];
    if (tid < N_DIM) clsb_s[tid] = clsb[tid];

    // ---- prologue: load ALL of B fp16 resident (96 rows x 1536 B)
    // 96*96 = 9216 chunks of 16B -> 36 per thread
#pragma unroll
    for (int j = 0; j < 36; j++) {
        int u = tid + 256 * j;
        int row = u / 96, ch = u - row * 96;
        cp16(sb + SM_BB + (uint32_t)row * B_RS + (uint32_t)ch * 16,
             g_Bh + (size_t)u * 16);
    }
    asm volatile("cp.async.commit_group;" ::: "memory");
    __syncthreads();   // idx_s visible

    // ---- producer A mapping: row-slot pr (0..15), float4 k-chunk pk ----
    const int pr = tid >> 4;
    const int pk = (tid & 15) << 2;
    const float* aP[8];
#pragma unroll
    for (int i = 0; i < 8; i++)
        aP[i] = seq + ((size_t)b * S_DIM + idx_s[pr + 16 * i]) * D_DIM + pk;
    uint32_t soA[8];
#pragma unroll
    for (int i = 0; i < 8; i++) soA[i] = (uint32_t)(pr + 16 * i) * A_RS + (uint32_t)pk * 2;

    // ---- consumer mapping: 4(M) x 2(N), warp tile 32x48 ----
    const int wm = (wid & 3) * 32;
    const int wn = (wid >> 2) * 48;
    const uint32_t aOff = (uint32_t)(wm + (lane & 15)) * A_RS + ((lane >> 4) << 4);
    const uint32_t bOff = (uint32_t)(wn + ((lane >> 4) << 3) + (lane & 7)) * B_RS
                        + (((lane >> 3) & 1) << 4);

    float acc[12][4];
#pragma unroll
    for (int i = 0; i < 12; i++)
#pragma unroll
        for (int v = 0; v < 4; v++) acc[i][v] = 0.f;

    // A(0) into regs; drain B prologue
    float4 ra[8];
#pragma unroll
    for (int i = 0; i < 8; i++) ra[i] = *(const float4*)(aP[i]);
    asm volatile("cp.async.wait_group 0;" ::: "memory");
    __syncthreads();   // B resident visible

    for (int t = 0; t < NUM_KT; t++) {
        const int p = t & 1;
        char* bufA = smem + SM_A + p * A_STAGE;

        // convert + store A(t)
#pragma unroll
        for (int i = 0; i < 8; i++) *(uint2*)(bufA + soA[i]) = cvt_f16x4(ra[i]);

        // prefetch A(t+1) (one full tile of latency cover)
        if (t + 1 < NUM_KT) {
            const int kg = (t + 1) * KT;
#pragma unroll
            for (int i = 0; i < 8; i++) ra[i] = *(const float4*)(aP[i] + kg);
        }
        __syncthreads();   // publish A(t); also orders reads(t-1) before store(t+1)

        const uint32_t sA = sb + SM_A + p * A_STAGE;
        const uint32_t bcol = (uint32_t)t * 128;   // 64 k * 2 B
#pragma unroll
        for (int ks = 0; ks < 4; ks++) {
            const uint32_t k0b = (uint32_t)ks * 32;
            uint32_t af[2][4];
#pragma unroll
            for (int i = 0; i < 2; i++)
                ldsm4(af[i], sA + aOff + i * (16 * A_RS) + k0b);
            uint32_t bf[3][4];
#pragma unroll
            for (int j = 0; j < 3; j++)
                ldsm4(bf[j], sb + SM_BB + bOff + j * (16 * B_RS) + bcol + k0b);
#pragma unroll
            for (int i = 0; i < 2; i++)
#pragma unroll
                for (int j2 = 0; j2 < 6; j2++)
                    mma_f16(acc[i * 6 + j2], af[i], &bf[j2 >> 1][(j2 & 1) * 2]);
        }
    }

    // ======== epilogue: smem transpose -> fully coalesced stores ========
    __syncthreads();   // all warps done with B region & A stages
    float* ep = (float*)(smem + SM_BB);   // reuse B region: [128 w][EP_RS]
#pragma unroll
    for (int i = 0; i < 2; i++) {
#pragma unroll
        for (int j2 = 0; j2 < 6; j2++) {
            const float* c = acc[i * 6 + j2];
#pragma unroll
            for (int v = 0; v < 4; v++) {
                const int w = wm + i * 16 + (lane >> 2) + 8 * (v >> 1);
                const int n = wn + j2 * 8 + 2 * (lane & 3) + (v & 1);
                ep[w * EP_RS + n] = c[v] + clsb_s[n];
            }
        }
    }
    __syncthreads();

    // each warp writes 4 a-chunks; per chunk: 384 consecutive floats (1536 B)
#pragma unroll
    for (int ci = 0; ci < 4; ci++) {
        const int a_ = wid * 4 + ci;          // 0..31
        float* dst = out + (size_t)a_ * (B_DIM * W_DIM * 3)
                         + (size_t)b * (W_DIM * 3) + (size_t)w0 * 3;
#pragma unroll
        for (int it = 0; it < 12; it++) {
            const int f = it * 32 + lane;     // 0..383
            const int r = f / 3;
            const int cc = f - r * 3;
            dst[f] = ep[r * EP_RS + a_ * 3 + cc];
        }
    }
}

extern "C" void kernel_launch(void* const* d_in, const int* in_sizes, int n_in,
                              void* d_out, int out_size) {
    const float* seq  = (const float*)d_in[0];  // [B, S, D] fp32
    const int*   widx = (const int*)d_in[1];    // [B, W] int32
    const float* clsw = (const float*)d_in[2];  // [A*3, D] fp32
    const float* clsb = (const float*)d_in[3];  // [A*3] fp32
    float* out = (float*)d_out;                 // [A, B, W, 3] fp32

    cvtB_kernel<<<36, 512>>>(clsw);
    cudaFuncSetAttribute(ner_hmma_kernel, cudaFuncAttributeMaxDynamicSharedMemorySize, SMEM_TOTAL);
    ner_hmma_kernel<<<128, THREADS, SMEM_TOTAL>>>(seq, widx, clsb, out);
}

// round 15
// speedup vs baseline: 1.1067x; 1.1067x over previous
#include <cuda_runtime.h>
#include <cstdint>

#define B_DIM 64
#define S_DIM 512
#define W_DIM 256
#define D_DIM 768
#define N_DIM 96
#define MT 128
#define KT 64
#define NUM_KT 12
#define THREADS 256

#define A_RS 144                      // A fp16 stage row stride
#define B_RS 1552                     // B resident row stride (768*2 + 16)
#define A_STAGE 18432                 // 128 * 144
#define SM_A 1024                     // after idx (512) + clsb (384)
#define SM_BB (SM_A + 2 * A_STAGE)    // 37888
#define SMEM_TOTAL (SM_BB + N_DIM * B_RS)   // 186880
#define EP_RS 100                     // epilogue smem row stride (floats)

// Pre-converted fp16 copy of clsw: [96][768] fp16 (linear, 1536 B rows)
__device__ __align__(16) unsigned char g_Bh[N_DIM * D_DIM * 2];

static __device__ __forceinline__ uint32_t smem_u32(const void* p) {
    uint32_t a;
    asm("{ .reg .u64 t; cvta.to.shared.u64 t, %1; cvt.u32.u64 %0, t; }" : "=r"(a) : "l"(p));
    return a;
}

static __device__ __forceinline__ void ldsm4(uint32_t* r, uint32_t addr) {
    asm volatile("ldmatrix.sync.aligned.m8n8.x4.shared.b16 {%0,%1,%2,%3}, [%4];"
                 : "=r"(r[0]), "=r"(r[1]), "=r"(r[2]), "=r"(r[3]) : "r"(addr));
}

static __device__ __forceinline__ void mma_f16(float* c, const uint32_t* a, const uint32_t* b) {
    asm volatile(
        "mma.sync.aligned.m16n8k16.row.col.f32.f16.f16.f32 "
        "{%0,%1,%2,%3}, {%4,%5,%6,%7}, {%8,%9}, {%0,%1,%2,%3};"
        : "+f"(c[0]), "+f"(c[1]), "+f"(c[2]), "+f"(c[3])
        : "r"(a[0]), "r"(a[1]), "r"(a[2]), "r"(a[3]), "r"(b[0]), "r"(b[1]));
}

static __device__ __forceinline__ uint2 cvt_f16x4(float4 v) {
    uint2 r;   // low half of each word = lower-k element
    asm("cvt.rn.f16x2.f32 %0, %1, %2;" : "=r"(r.x) : "f"(v.y), "f"(v.x));
    asm("cvt.rn.f16x2.f32 %0, %1, %2;" : "=r"(r.y) : "f"(v.w), "f"(v.z));
    return r;
}

static __device__ __forceinline__ void cp16(uint32_t dst, const void* src) {
    asm volatile("cp.async.cg.shared.global [%0], [%1], 16;" :: "r"(dst), "l"(src) : "memory");
}

// ---------- kernel 1: convert clsw fp32 -> fp16 scratch ----------
__global__ void cvtB_kernel(const float* __restrict__ clsw) {
    int i = blockIdx.x * blockDim.x + threadIdx.x;   // 18432 float4 chunks
    float4 v = ((const float4*)clsw)[i];
    ((uint2*)g_Bh)[i] = cvt_f16x4(v);
}

// ---------- kernel 2: gathered GEMM, depth-2 A prefetch ----------
__global__ __launch_bounds__(THREADS, 1)
void ner_hmma_kernel(const float* __restrict__ seq, const int* __restrict__ widx,
                     const float* __restrict__ clsb, float* __restrict__ out) {
    extern __shared__ char smem[];
    const uint32_t sb = smem_u32(smem);
    const int tid  = threadIdx.x;
    const int wid  = tid >> 5;
    const int lane = tid & 31;
    const int b  = blockIdx.x >> 1;
    const int w0 = (blockIdx.x & 1) * MT;

    int*   idx_s  = (int*)smem;                 // [0, 512)
    float* clsb_s = (float*)(smem + 512);       // [512, 896)
    if (tid < MT)    idx_s[tid]  = widx[b * W_DIM + w0 + tid];
    if (tid < N_DIM) clsb_s[tid] = clsb[tid];

    // ---- prologue: load ALL of B fp16 resident (96 rows x 1536 B)
    // 9216 chunks of 16B -> 36 per thread
#pragma unroll
    for (int j = 0; j < 36; j++) {
        int u = tid + 256 * j;
        int row = u / 96, ch = u - row * 96;
        cp16(sb + SM_BB + (uint32_t)row * B_RS + (uint32_t)ch * 16,
             g_Bh + (size_t)u * 16);
    }
    asm volatile("cp.async.commit_group;" ::: "memory");
    __syncthreads();   // idx_s visible

    // ---- producer A mapping: row-slot pr (0..15), float4 k-chunk pk ----
    const int pr = tid >> 4;
    const int pk = (tid & 15) << 2;
    const float* aP[8];
#pragma unroll
    for (int i = 0; i < 8; i++)
        aP[i] = seq + ((size_t)b * S_DIM + idx_s[pr + 16 * i]) * D_DIM + pk;
    uint32_t soA[8];
#pragma unroll
    for (int i = 0; i < 8; i++) soA[i] = (uint32_t)(pr + 16 * i) * A_RS + (uint32_t)pk * 2;

    // ---- consumer mapping: 4(M) x 2(N), warp tile 32x48 ----
    const int wm = (wid & 3) * 32;
    const int wn = (wid >> 2) * 48;
    const uint32_t aOff = (uint32_t)(wm + (lane & 15)) * A_RS + ((lane >> 4) << 4);
    const uint32_t bOff = (uint32_t)(wn + ((lane >> 4) << 3) + (lane & 7)) * B_RS
                        + (((lane >> 3) & 1) << 4);

    float acc[12][4];
#pragma unroll
    for (int i = 0; i < 12; i++)
#pragma unroll
        for (int v = 0; v < 4; v++) acc[i][v] = 0.f;

    // ---- depth-2 A prefetch: tiles 0 and 1 both in flight ----
    float4 ra[2][8];
#pragma unroll
    for (int i = 0; i < 8; i++) ra[0][i] = *(const float4*)(aP[i]);
#pragma unroll
    for (int i = 0; i < 8; i++) ra[1][i] = *(const float4*)(aP[i] + KT);

    asm volatile("cp.async.wait_group 0;" ::: "memory");
    __syncthreads();   // B resident visible

    for (int t = 0; t < NUM_KT; t++) {
        const int p = t & 1;
        char* bufA = smem + SM_A + p * A_STAGE;

        // convert + store A(t) from buffer t&1
#pragma unroll
        for (int i = 0; i < 8; i++) *(uint2*)(bufA + soA[i]) = cvt_f16x4(ra[p][i]);

        // refill: issue LDGs for tile t+2 (A(t+1) still in flight -> depth 2)
        if (t + 2 < NUM_KT) {
            const int kg = (t + 2) * KT;
#pragma unroll
            for (int i = 0; i < 8; i++) ra[p][i] = *(const float4*)(aP[i] + kg);
        }
        __syncthreads();   // publish A(t); orders reads(t-1) before store(t+1)

        const uint32_t sA = sb + SM_A + p * A_STAGE;
        const uint32_t bcol = (uint32_t)t * 128;   // 64 k * 2 B
#pragma unroll
        for (int ks = 0; ks < 4; ks++) {
            const uint32_t k0b = (uint32_t)ks * 32;
            uint32_t af[2][4];
#pragma unroll
            for (int i = 0; i < 2; i++)
                ldsm4(af[i], sA + aOff + i * (16 * A_RS) + k0b);
            uint32_t bf[3][4];
#pragma unroll
            for (int j = 0; j < 3; j++)
                ldsm4(bf[j], sb + SM_BB + bOff + j * (16 * B_RS) + bcol + k0b);
#pragma unroll
            for (int i = 0; i < 2; i++)
#pragma unroll
                for (int j2 = 0; j2 < 6; j2++)
                    mma_f16(acc[i * 6 + j2], af[i], &bf[j2 >> 1][(j2 & 1) * 2]);
        }
    }

    // ======== epilogue: smem transpose -> fully coalesced stores ========
    __syncthreads();   // all warps done with B region & A stages
    float* ep = (float*)(smem + SM_BB);   // reuse B region: [128 w][EP_RS]
#pragma unroll
    for (int i = 0; i < 2; i++) {
#pragma unroll
        for (int j2 = 0; j2 < 6; j2++) {
            const float* c = acc[i * 6 + j2];
#pragma unroll
            for (int v = 0; v < 4; v++) {
                const int w = wm + i * 16 + (lane >> 2) + 8 * (v >> 1);
                const int n = wn + j2 * 8 + 2 * (lane & 3) + (v & 1);
                ep[w * EP_RS + n] = c[v] + clsb_s[n];
            }
        }
    }
    __syncthreads();

    // each warp writes 4 a-chunks; per chunk: 384 consecutive floats (1536 B)
#pragma unroll
    for (int ci = 0; ci < 4; ci++) {
        const int a_ = wid * 4 + ci;          // 0..31
        float* dst = out + (size_t)a_ * (B_DIM * W_DIM * 3)
                         + (size_t)b * (W_DIM * 3) + (size_t)w0 * 3;
#pragma unroll
        for (int it = 0; it < 12; it++) {
            const int f = it * 32 + lane;     // 0..383
            const int r = f / 3;
            const int cc = f - r * 3;
            dst[f] = ep[r * EP_RS + a_ * 3 + cc];
        }
    }
}

extern "C" void kernel_launch(void* const* d_in, const int* in_sizes, int n_in,
                              void* d_out, int out_size) {
    const float* seq  = (const float*)d_in[0];  // [B, S, D] fp32
    const int*   widx = (const int*)d_in[1];    // [B, W] int32
    const float* clsw = (const float*)d_in[2];  // [A*3, D] fp32
    const float* clsb = (const float*)d_in[3];  // [A*3] fp32
    float* out = (float*)d_out;                 // [A, B, W, 3] fp32

    cvtB_kernel<<<36, 512>>>(clsw);
    cudaFuncSetAttribute(ner_hmma_kernel, cudaFuncAttributeMaxDynamicSharedMemorySize, SMEM_TOTAL);
    ner_hmma_kernel<<<128, THREADS, SMEM_TOTAL>>>(seq, widx, clsb, out);
}

// round 16
// speedup vs baseline: 1.2411x; 1.1215x over previous
#include <cuda_runtime.h>
#include <cstdint>

#define B_DIM 64
#define S_DIM 512
#define W_DIM 256
#define D_DIM 768
#define N_DIM 96
#define MT 128
#define KT 64
#define NUM_KT 12
#define THREADS 256

#define A_RS 144                      // A fp16 stage row stride
#define B_RS 1552                     // B resident row stride (768*2 + 16)
#define A_STAGE 18432                 // 128 * 144
#define SM_A 1024                     // after idx (512) + clsb (384)
#define SM_BB (SM_A + 2 * A_STAGE)    // 37888
#define SMEM_TOTAL (SM_BB + N_DIM * B_RS)   // 186880
#define EP_RS 100                     // epilogue smem row stride (floats)

static __device__ __forceinline__ uint32_t smem_u32(const void* p) {
    uint32_t a;
    asm("{ .reg .u64 t; cvta.to.shared.u64 t, %1; cvt.u32.u64 %0, t; }" : "=r"(a) : "l"(p));
    return a;
}

static __device__ __forceinline__ void ldsm4(uint32_t* r, uint32_t addr) {
    asm volatile("ldmatrix.sync.aligned.m8n8.x4.shared.b16 {%0,%1,%2,%3}, [%4];"
                 : "=r"(r[0]), "=r"(r[1]), "=r"(r[2]), "=r"(r[3]) : "r"(addr));
}

static __device__ __forceinline__ void mma_f16(float* c, const uint32_t* a, const uint32_t* b) {
    asm volatile(
        "mma.sync.aligned.m16n8k16.row.col.f32.f16.f16.f32 "
        "{%0,%1,%2,%3}, {%4,%5,%6,%7}, {%8,%9}, {%0,%1,%2,%3};"
        : "+f"(c[0]), "+f"(c[1]), "+f"(c[2]), "+f"(c[3])
        : "r"(a[0]), "r"(a[1]), "r"(a[2]), "r"(a[3]), "r"(b[0]), "r"(b[1]));
}

static __device__ __forceinline__ uint2 cvt_f16x4(float4 v) {
    uint2 r;   // low half of each word = lower-k element
    asm("cvt.rn.f16x2.f32 %0, %1, %2;" : "=r"(r.x) : "f"(v.y), "f"(v.x));
    asm("cvt.rn.f16x2.f32 %0, %1, %2;" : "=r"(r.y) : "f"(v.w), "f"(v.z));
    return r;
}

// ---------- single kernel: gathered GEMM ----------
__global__ __launch_bounds__(THREADS, 1)
void ner_hmma_kernel(const float* __restrict__ seq, const int* __restrict__ widx,
                     const float* __restrict__ clsw, const float* __restrict__ clsb,
                     float* __restrict__ out) {
    extern __shared__ char smem[];
    const uint32_t sb = smem_u32(smem);
    const int tid  = threadIdx.x;
    const int wid  = tid >> 5;
    const int lane = tid & 31;
    const int b  = blockIdx.x >> 1;
    const int w0 = (blockIdx.x & 1) * MT;

    int*   idx_s  = (int*)smem;                 // [0, 512)
    float* clsb_s = (float*)(smem + 512);       // [512, 896)
    if (tid < MT)    idx_s[tid]  = widx[b * W_DIM + w0 + tid];
    if (tid < N_DIM) clsb_s[tid] = clsb[tid];
    __syncthreads();   // idx_s visible

    // ---- producer A mapping: row-slot pr (0..15), float4 k-chunk pk ----
    const int pr = tid >> 4;
    const int pk = (tid & 15) << 2;
    const float* aP[8];
#pragma unroll
    for (int i = 0; i < 8; i++)
        aP[i] = seq + ((size_t)b * S_DIM + idx_s[pr + 16 * i]) * D_DIM + pk;
    uint32_t soA[8];
#pragma unroll
    for (int i = 0; i < 8; i++) soA[i] = (uint32_t)(pr + 16 * i) * A_RS + (uint32_t)pk * 2;

    // ---- depth-2 A prefetch: tiles 0 and 1 both in flight FIRST ----
    float4 ra[2][8];
#pragma unroll
    for (int i = 0; i < 8; i++) ra[0][i] = *(const float4*)(aP[i]);
#pragma unroll
    for (int i = 0; i < 8; i++) ra[1][i] = *(const float4*)(aP[i] + KT);

    // ---- prologue: convert ALL of B fp32 -> fp16 resident smem ----
    // clsw = 18432 float4 chunks; 72/thread. Reads are L2-broadcast across
    // CTAs; work overlaps the A(0)/A(1) gather LDGs already in flight.
#pragma unroll 8
    for (int j = 0; j < 72; j++) {
        int i = tid + 256 * j;
        int row = i / 192, rem = i - row * 192;
        float4 v = ((const float4*)clsw)[i];
        *(uint2*)(smem + SM_BB + (uint32_t)row * B_RS + (uint32_t)rem * 8) = cvt_f16x4(v);
    }

    // ---- consumer mapping: 4(M) x 2(N), warp tile 32x48 ----
    const int wm = (wid & 3) * 32;
    const int wn = (wid >> 2) * 48;
    const uint32_t aOff = (uint32_t)(wm + (lane & 15)) * A_RS + ((lane >> 4) << 4);
    const uint32_t bOff = (uint32_t)(wn + ((lane >> 4) << 3) + (lane & 7)) * B_RS
                        + (((lane >> 3) & 1) << 4);

    float acc[12][4];
#pragma unroll
    for (int i = 0; i < 12; i++)
#pragma unroll
        for (int v = 0; v < 4; v++) acc[i][v] = 0.f;

    __syncthreads();   // B resident visible to all warps

    for (int t = 0; t < NUM_KT; t++) {
        const int p = t & 1;
        char* bufA = smem + SM_A + p * A_STAGE;

        // convert + store A(t) from register buffer p
#pragma unroll
        for (int i = 0; i < 8; i++) *(uint2*)(bufA + soA[i]) = cvt_f16x4(ra[p][i]);

        // refill: issue LDGs for tile t+2 (A(t+1) still in flight -> depth 2)
        if (t + 2 < NUM_KT) {
            const int kg = (t + 2) * KT;
#pragma unroll
            for (int i = 0; i < 8; i++) ra[p][i] = *(const float4*)(aP[i] + kg);
        }
        __syncthreads();   // publish A(t); orders reads(t-1) before store(t+1)

        const uint32_t sA = sb + SM_A + p * A_STAGE;
        const uint32_t bcol = (uint32_t)t * 128;   // 64 k * 2 B
#pragma unroll
        for (int ks = 0; ks < 4; ks++) {
            const uint32_t k0b = (uint32_t)ks * 32;
            uint32_t af[2][4];
#pragma unroll
            for (int i = 0; i < 2; i++)
                ldsm4(af[i], sA + aOff + i * (16 * A_RS) + k0b);
            uint32_t bf[3][4];
#pragma unroll
            for (int j = 0; j < 3; j++)
                ldsm4(bf[j], sb + SM_BB + bOff + j * (16 * B_RS) + bcol + k0b);
#pragma unroll
            for (int i = 0; i < 2; i++)
#pragma unroll
                for (int j2 = 0; j2 < 6; j2++)
                    mma_f16(acc[i * 6 + j2], af[i], &bf[j2 >> 1][(j2 & 1) * 2]);
        }
    }

    // ======== epilogue: smem transpose -> fully coalesced stores ========
    __syncthreads();   // all warps done with B region & A stages
    float* ep = (float*)(smem + SM_BB);   // reuse B region: [128 w][EP_RS]
#pragma unroll
    for (int i = 0; i < 2; i++) {
#pragma unroll
        for (int j2 = 0; j2 < 6; j2++) {
            const float* c = acc[i * 6 + j2];
#pragma unroll
            for (int v = 0; v < 4; v++) {
                const int w = wm + i * 16 + (lane >> 2) + 8 * (v >> 1);
                const int n = wn + j2 * 8 + 2 * (lane & 3) + (v & 1);
                ep[w * EP_RS + n] = c[v] + clsb_s[n];
            }
        }
    }
    __syncthreads();

    // each warp writes 4 a-chunks; per chunk: 384 consecutive floats (1536 B)
#pragma unroll
    for (int ci = 0; ci < 4; ci++) {
        const int a_ = wid * 4 + ci;          // 0..31
        float* dst = out + (size_t)a_ * (B_DIM * W_DIM * 3)
                         + (size_t)b * (W_DIM * 3) + (size_t)w0 * 3;
#pragma unroll
        for (int it = 0; it < 12; it++) {
            const int f = it * 32 + lane;     // 0..383
            const int r = f / 3;
            const int cc = f - r * 3;
            dst[f] = ep[r * EP_RS + a_ * 3 + cc];
        }
    }
}

extern "C" void kernel_launch(void* const* d_in, const int* in_sizes, int n_in,
                              void* d_out, int out_size) {
    const float* seq  = (const float*)d_in[0];  // [B, S, D] fp32
    const int*   widx = (const int*)d_in[1];    // [B, W] int32
    const float* clsw = (const float*)d_in[2];  // [A*3, D] fp32
    const float* clsb = (const float*)d_in[3];  // [A*3] fp32
    float* out = (float*)d_out;                 // [A, B, W, 3] fp32

    cudaFuncSetAttribute(ner_hmma_kernel, cudaFuncAttributeMaxDynamicSharedMemorySize, SMEM_TOTAL);
    ner_hmma_kernel<<<128, THREADS, SMEM_TOTAL>>>(seq, widx, clsw, clsb, out);
}